// round 4
// baseline (speedup 1.0000x reference)
#include <cuda_runtime.h>
#include <cuda_bf16.h>
#include <cstdint>

#define BATCH   2
#define SEQLEN  2048
#define DMODEL  1024
#define DSTATE  16
#define DTRANK  64
#define NROWS   (BATCH * SEQLEN)          // 4096
#define NCHUNK  64
#define CLEN    (SEQLEN / NCHUNK)         // 32
#define NCH     (BATCH * DMODEL)          // 2048 channels
#define NGRP    (NCH * NCHUNK)            // 131072 (channel,chunk) groups

// ---------------------------------------------------------------------------
// Device scratch
// ---------------------------------------------------------------------------
__device__ float  g_wp [96 * DMODEL];                        // W * sig(te)
__device__ float  g_A  [DMODEL * DSTATE];                    // -exp(A_log)
__device__ float  g_bp [(size_t)NROWS * DSTATE];             // B plane [b*L+l][n]
__device__ float  g_cp [(size_t)NROWS * DSTATE];             // C plane
__device__ float2 g_dd [(size_t)NROWS * DMODEL];             // [b][l][d] = (delta, delta*u)
__device__ float  g_hl [(size_t)NGRP * DSTATE];              // chunk-local final states
__device__ float  g_T  [(size_t)NGRP];                       // chunk delta sums
__device__ float  g_hin[(size_t)NGRP * DSTATE];              // chunk incoming states

// ---------------------------------------------------------------------------
// K0: fold sigmoid(trend) into x_proj_w; precompute A = -exp(A_log)
// ---------------------------------------------------------------------------
__global__ __launch_bounds__(256)
void prep_kernel(const float* __restrict__ W, const float* __restrict__ te,
                 const float* __restrict__ A_log)
{
    int idx = blockIdx.x * 256 + threadIdx.x;
    if (idx < 96 * DMODEL) {
        int k = idx & (DMODEL - 1);
        float sg = 1.f / (1.f + __expf(-te[k]));
        g_wp[idx] = W[idx] * sg;
    }
    if (idx < DMODEL * DSTATE) {
        g_A[idx] = -__expf(A_log[idx]);
    }
}

// ---------------------------------------------------------------------------
// K1 (fused): per 32-row block:
//   Phase 1: xz = x @ wp^T (32x96), keep dp (cols<64) in smem, B/C -> global
//   Phase 2: for 8 d-tiles of 128: delta = softplus(dp @ dtw_tile^T + b),
//            u = x*sig(te), write g_dd[(r,d)] = (delta, delta*u)
//   256 threads, grid = 128 blocks.
// ---------------------------------------------------------------------------
__global__ __launch_bounds__(256)
void fused12_kernel(const float* __restrict__ x,
                    const float* __restrict__ dtw,
                    const float* __restrict__ dtb,
                    const float* __restrict__ te)
{
    // smem: [0,2112)   phase1 As[64][33]  -> phase2 dps[64][33]
    //       [2112, +)  phase1 Ws[64][97]  -> phase2 wt[64][132]
    __shared__ float smbuf[2112 + 8448];
    float (*As)[33]  = (float(*)[33]) smbuf;
    float (*dps)[33] = (float(*)[33]) smbuf;
    float (*Ws)[97]  = (float(*)[97]) (smbuf + 2112);
    float (*wt)[132] = (float(*)[132])(smbuf + 2112);

    const int tid  = threadIdx.x;
    const int row0 = blockIdx.x * 32;
    const int ty   = tid >> 4;         // 0..15
    const int tx   = tid & 15;         // 0..15

    // ---------------- Phase 1: 32x96 projection ----------------
    float acc[2][6];
#pragma unroll
    for (int i = 0; i < 2; i++)
#pragma unroll
        for (int j = 0; j < 6; j++) acc[i][j] = 0.f;

    for (int kt = 0; kt < DMODEL; kt += 64) {
#pragma unroll
        for (int i = 0; i < 2; i++) {
            int e  = i * 256 + tid;
            int r  = e >> 4;
            int k4 = e & 15;
            float4 v = *(const float4*)&x[(size_t)(row0 + r) * DMODEL + kt + k4 * 4];
            As[k4 * 4 + 0][r] = v.x;
            As[k4 * 4 + 1][r] = v.y;
            As[k4 * 4 + 2][r] = v.z;
            As[k4 * 4 + 3][r] = v.w;
        }
#pragma unroll
        for (int i = 0; i < 6; i++) {
            int e  = i * 256 + tid;
            int c  = e >> 4;
            int k4 = e & 15;
            float4 v = *(const float4*)&g_wp[(size_t)c * DMODEL + kt + k4 * 4];
            Ws[k4 * 4 + 0][c] = v.x;
            Ws[k4 * 4 + 1][c] = v.y;
            Ws[k4 * 4 + 2][c] = v.z;
            Ws[k4 * 4 + 3][c] = v.w;
        }
        __syncthreads();

#pragma unroll 16
        for (int k = 0; k < 64; k++) {
            float a0 = As[k][ty * 2 + 0];
            float a1 = As[k][ty * 2 + 1];
            float wv[6];
#pragma unroll
            for (int j = 0; j < 6; j++) wv[j] = Ws[k][tx * 6 + j];
#pragma unroll
            for (int j = 0; j < 6; j++) {
                acc[0][j] = fmaf(a0, wv[j], acc[0][j]);
                acc[1][j] = fmaf(a1, wv[j], acc[1][j]);
            }
        }
        __syncthreads();
    }

    // epilogue: dp -> smem (k-major), B/C -> global
#pragma unroll
    for (int i = 0; i < 2; i++) {
        int rl = ty * 2 + i;
        int r  = row0 + rl;
#pragma unroll
        for (int j = 0; j < 6; j++) {
            int c = tx * 6 + j;
            float v = acc[i][j];
            if (c < DTRANK)                 dps[c][rl] = v;
            else if (c < DTRANK + DSTATE)   g_bp[(size_t)r * DSTATE + (c - DTRANK)] = v;
            else                            g_cp[(size_t)r * DSTATE + (c - DTRANK - DSTATE)] = v;
        }
    }
    __syncthreads();

    // ---------------- Phase 2: 8 d-tiles of 128 ----------------
    for (int dt = 0; dt < 8; dt++) {
        const int c0t = dt * 128;
        // load dtw tile: 128 cols x 64 k
#pragma unroll
        for (int i = 0; i < 8; i++) {
            int e  = i * 256 + tid;
            int c  = e >> 4;
            int k4 = e & 15;
            float4 v = *(const float4*)&dtw[(size_t)(c0t + c) * DTRANK + k4 * 4];
            wt[k4 * 4 + 0][c] = v.x;
            wt[k4 * 4 + 1][c] = v.y;
            wt[k4 * 4 + 2][c] = v.z;
            wt[k4 * 4 + 3][c] = v.w;
        }
        __syncthreads();

        float a2[2][8];
#pragma unroll
        for (int i = 0; i < 2; i++)
#pragma unroll
            for (int j = 0; j < 8; j++) a2[i][j] = 0.f;

#pragma unroll 16
        for (int k = 0; k < 64; k++) {
            float a0 = dps[k][ty * 2 + 0];
            float a1 = dps[k][ty * 2 + 1];
            float4 w0 = *(const float4*)&wt[k][tx * 8];
            float4 w1 = *(const float4*)&wt[k][tx * 8 + 4];
            float wv[8] = {w0.x, w0.y, w0.z, w0.w, w1.x, w1.y, w1.z, w1.w};
#pragma unroll
            for (int j = 0; j < 8; j++) {
                a2[0][j] = fmaf(a0, wv[j], a2[0][j]);
                a2[1][j] = fmaf(a1, wv[j], a2[1][j]);
            }
        }

        // epilogue: softplus + u, write g_dd (x re-read is an L2 hit)
#pragma unroll
        for (int i = 0; i < 2; i++) {
            int r  = row0 + ty * 2 + i;
            int c0 = c0t + tx * 8;
            float4 x0 = *(const float4*)&x[(size_t)r * DMODEL + c0];
            float4 x1 = *(const float4*)&x[(size_t)r * DMODEL + c0 + 4];
            float xv[8] = {x0.x, x0.y, x0.z, x0.w, x1.x, x1.y, x1.z, x1.w};
            float dl[8], du[8];
#pragma unroll
            for (int j = 0; j < 8; j++) {
                int c = c0 + j;
                float sg = 1.f / (1.f + __expf(-te[c]));
                float u  = xv[j] * sg;
                float v  = a2[i][j] + dtb[c];
                float delta = fmaxf(v, 0.f) + log1pf(__expf(-fabsf(v)));
                dl[j] = delta;
                du[j] = delta * u;
            }
            float4* dst = (float4*)&g_dd[(size_t)r * DMODEL + c0];
#pragma unroll
            for (int j = 0; j < 4; j++)
                dst[j] = make_float4(dl[2*j], du[2*j], dl[2*j+1], du[2*j+1]);
        }
        __syncthreads();
    }
}

// ---------------------------------------------------------------------------
// K2 (pass A): thread = (b, d, chunk), 16 states in registers, MLP=8 batches.
//   grid = 2 * 4 * 64 = 512 blocks, 256 threads.
// ---------------------------------------------------------------------------
__global__ __launch_bounds__(256)
void scanA_kernel()
{
    __shared__ float Bs[CLEN][DSTATE];   // 2KB

    const int tid   = threadIdx.x;
    const int blk   = blockIdx.x;
    const int b     = blk >> 8;
    const int rem   = blk & 255;
    const int dgrp  = rem >> 6;
    const int chunk = rem & 63;
    const int d     = dgrp * 256 + tid;
    const int ch    = b * DMODEL + d;
    const int gid   = ch * NCHUNK + chunk;
    const int l0    = chunk * CLEN;

    if (tid < CLEN * DSTATE / 4) {
        const float4* src = (const float4*)&g_bp[((size_t)b * SEQLEN + l0) * DSTATE];
        ((float4*)Bs)[tid] = src[tid];
    }

    float A[DSTATE];
#pragma unroll
    for (int n = 0; n < DSTATE; n++) A[n] = g_A[(size_t)d * DSTATE + n];
    bool uniform = true;
#pragma unroll
    for (int n = 1; n < DSTATE; n++) uniform &= (A[n] == A[0]);

    float h[DSTATE];
#pragma unroll
    for (int n = 0; n < DSTATE; n++) h[n] = 0.f;
    float T = 0.f;

    const float2* __restrict__ dd = g_dd + ((size_t)b * SEQLEN + l0) * DMODEL + d;
    __syncthreads();

    if (uniform) {
        const float A0 = A[0];
        for (int lb = 0; lb < CLEN / 8; lb++) {
            float2 t[8];
#pragma unroll
            for (int i = 0; i < 8; i++) t[i] = dd[(size_t)(lb * 8 + i) * DMODEL];
            float a[8];
#pragma unroll
            for (int i = 0; i < 8; i++) { a[i] = __expf(t[i].x * A0); T += t[i].x; }
#pragma unroll
            for (int i = 0; i < 8; i++) {
                int l = lb * 8 + i;
#pragma unroll
                for (int n = 0; n < DSTATE; n++)
                    h[n] = fmaf(a[i], h[n], t[i].y * Bs[l][n]);
            }
        }
    } else {
        for (int lb = 0; lb < CLEN / 8; lb++) {
            float2 t[8];
#pragma unroll
            for (int i = 0; i < 8; i++) t[i] = dd[(size_t)(lb * 8 + i) * DMODEL];
#pragma unroll
            for (int i = 0; i < 8; i++) {
                int l = lb * 8 + i;
                T += t[i].x;
#pragma unroll
                for (int n = 0; n < DSTATE; n++)
                    h[n] = fmaf(__expf(t[i].x * A[n]), h[n], t[i].y * Bs[l][n]);
            }
        }
    }

#pragma unroll
    for (int n = 0; n < DSTATE; n++) g_hl[(size_t)gid * DSTATE + n] = h[n];
    g_T[gid] = T;
}

// ---------------------------------------------------------------------------
// K3 (pass B): sequential chunk combine per (channel, n). 32768 threads.
// ---------------------------------------------------------------------------
__global__ __launch_bounds__(256)
void scanB_kernel()
{
    const int idx = blockIdx.x * 256 + threadIdx.x;
    const int ch  = idx >> 4;
    const int n   = idx & 15;
    const int d   = ch & (DMODEL - 1);

    const float A = g_A[(size_t)d * DSTATE + n];

    float hin = 0.f;
#pragma unroll 8
    for (int j = 0; j < NCHUNK; j++) {
        size_t g = (size_t)ch * NCHUNK + j;
        g_hin[g * DSTATE + n] = hin;
        hin = g_hl[g * DSTATE + n] + hin * __expf(g_T[g] * A);
    }
}

// ---------------------------------------------------------------------------
// K4 (pass C): full re-scan with correct h0; coalesced y output, MLP=8.
// ---------------------------------------------------------------------------
__global__ __launch_bounds__(256)
void scanC_kernel(const float* __restrict__ x,
                  const float* __restrict__ te,
                  const float* __restrict__ Dp,
                  float* __restrict__ out)
{
    __shared__ float Bs[CLEN][DSTATE];
    __shared__ float Cs[CLEN][DSTATE];

    const int tid   = threadIdx.x;
    const int blk   = blockIdx.x;
    const int b     = blk >> 8;
    const int rem   = blk & 255;
    const int dgrp  = rem >> 6;
    const int chunk = rem & 63;
    const int d     = dgrp * 256 + tid;
    const int ch    = b * DMODEL + d;
    const int gid   = ch * NCHUNK + chunk;
    const int l0    = chunk * CLEN;

    if (tid < CLEN * DSTATE / 4) {
        const float4* sb = (const float4*)&g_bp[((size_t)b * SEQLEN + l0) * DSTATE];
        ((float4*)Bs)[tid] = sb[tid];
    } else if (tid < CLEN * DSTATE / 2) {
        const float4* sc = (const float4*)&g_cp[((size_t)b * SEQLEN + l0) * DSTATE];
        ((float4*)Cs)[tid - CLEN * DSTATE / 4] = sc[tid - CLEN * DSTATE / 4];
    }

    float A[DSTATE];
#pragma unroll
    for (int n = 0; n < DSTATE; n++) A[n] = g_A[(size_t)d * DSTATE + n];
    bool uniform = true;
#pragma unroll
    for (int n = 1; n < DSTATE; n++) uniform &= (A[n] == A[0]);

    float h[DSTATE];
#pragma unroll
    for (int n = 0; n < DSTATE; n++) h[n] = g_hin[(size_t)gid * DSTATE + n];

    const float sgD = (1.f / (1.f + __expf(-te[d]))) * Dp[d];

    const float2* __restrict__ dd = g_dd + ((size_t)b * SEQLEN + l0) * DMODEL + d;
    const float*  __restrict__ xp = x    + ((size_t)b * SEQLEN + l0) * DMODEL + d;
    float*        __restrict__ op = out  + ((size_t)b * SEQLEN + l0) * DMODEL + d;
    __syncthreads();

    if (uniform) {
        const float A0 = A[0];
        for (int lb = 0; lb < CLEN / 8; lb++) {
            float2 t[8];
            float  xv[8];
#pragma unroll
            for (int i = 0; i < 8; i++) t[i]  = dd[(size_t)(lb * 8 + i) * DMODEL];
#pragma unroll
            for (int i = 0; i < 8; i++) xv[i] = xp[(size_t)(lb * 8 + i) * DMODEL];
            float a[8];
#pragma unroll
            for (int i = 0; i < 8; i++) a[i] = __expf(t[i].x * A0);
#pragma unroll
            for (int i = 0; i < 8; i++) {
                int l = lb * 8 + i;
                float y = 0.f;
#pragma unroll
                for (int n = 0; n < DSTATE; n++) {
                    h[n] = fmaf(a[i], h[n], t[i].y * Bs[l][n]);
                    y    = fmaf(h[n], Cs[l][n], y);
                }
                op[(size_t)l * DMODEL] = fmaf(xv[i], sgD, y);
            }
        }
    } else {
        for (int lb = 0; lb < CLEN / 8; lb++) {
            float2 t[8];
            float  xv[8];
#pragma unroll
            for (int i = 0; i < 8; i++) t[i]  = dd[(size_t)(lb * 8 + i) * DMODEL];
#pragma unroll
            for (int i = 0; i < 8; i++) xv[i] = xp[(size_t)(lb * 8 + i) * DMODEL];
#pragma unroll
            for (int i = 0; i < 8; i++) {
                int l = lb * 8 + i;
                float y = 0.f;
#pragma unroll
                for (int n = 0; n < DSTATE; n++) {
                    h[n] = fmaf(__expf(t[i].x * A[n]), h[n], t[i].y * Bs[l][n]);
                    y    = fmaf(h[n], Cs[l][n], y);
                }
                op[(size_t)l * DMODEL] = fmaf(xv[i], sgD, y);
            }
        }
    }
}

// ---------------------------------------------------------------------------
// Launch
// ---------------------------------------------------------------------------
extern "C" void kernel_launch(void* const* d_in, const int* in_sizes, int n_in,
                              void* d_out, int out_size)
{
    const float* x    = (const float*)d_in[0];
    const float* Alog = (const float*)d_in[1];
    const float* xpw  = (const float*)d_in[2];
    const float* dtw  = (const float*)d_in[3];
    const float* dtb  = (const float*)d_in[4];
    const float* Dp   = (const float*)d_in[5];
    const float* te   = (const float*)d_in[6];
    float* out = (float*)d_out;

    prep_kernel  <<<(96 * DMODEL + 255) / 256, 256>>>(xpw, te, Alog);
    fused12_kernel<<<NROWS / 32, 256>>>(x, dtw, dtb, te);
    scanA_kernel <<<BATCH * 4 * NCHUNK, 256>>>();
    scanB_kernel <<<(NCH * DSTATE) / 256, 256>>>();
    scanC_kernel <<<BATCH * 4 * NCHUNK, 256>>>(x, te, Dp, out);
}

// round 5
// speedup vs baseline: 1.6657x; 1.6657x over previous
#include <cuda_runtime.h>
#include <cuda_bf16.h>
#include <cstdint>

#define BATCH   2
#define SEQLEN  2048
#define DMODEL  1024
#define DSTATE  16
#define DTRANK  64
#define NROWS   (BATCH * SEQLEN)          // 4096
#define NCHUNK  64
#define CLEN    (SEQLEN / NCHUNK)         // 32
#define NCH     (BATCH * DMODEL)          // 2048 channels
#define NGRP    (NCH * NCHUNK)            // 131072

// ---------------------------------------------------------------------------
// Device scratch
// ---------------------------------------------------------------------------
__device__ float  g_wp [96 * DMODEL];                        // W * sig(te)
__device__ float  g_A  [DMODEL * DSTATE];                    // -exp(A_log)
__device__ float  g_dp [(size_t)NROWS * DTRANK];             // delta_part
__device__ float  g_bp [(size_t)NROWS * DSTATE];             // B plane
__device__ float  g_cp [(size_t)NROWS * DSTATE];             // C plane
__device__ float2 g_dd [(size_t)NROWS * DMODEL];             // (delta, delta*u)
__device__ float  g_hl [(size_t)NGRP * DSTATE];              // chunk-local states
__device__ float  g_T  [(size_t)NGRP];                       // chunk delta sums
__device__ float  g_hin[(size_t)NGRP * DSTATE];              // chunk incoming states

// ---------------------------------------------------------------------------
// K0: fold sigmoid(trend) into x_proj_w; precompute A = -exp(A_log)
// ---------------------------------------------------------------------------
__global__ __launch_bounds__(256)
void prep_kernel(const float* __restrict__ W, const float* __restrict__ te,
                 const float* __restrict__ A_log)
{
    int idx = blockIdx.x * 256 + threadIdx.x;
    if (idx < 96 * DMODEL) {
        int k = idx & (DMODEL - 1);
        float sg = 1.f / (1.f + __expf(-te[k]));
        g_wp[idx] = W[idx] * sg;
    }
    if (idx < DMODEL * DSTATE) {
        g_A[idx] = -__expf(A_log[idx]);
    }
}

// ---------------------------------------------------------------------------
// K1: xz = x @ wp^T   (M=4096, N=96, K=1024)  BM=32 BN=96 BK=64, 256 thr
// ---------------------------------------------------------------------------
__global__ __launch_bounds__(256)
void gemm1_kernel(const float* __restrict__ x)
{
    __shared__ float As[64][33];
    __shared__ float Ws[64][97];

    const int tid  = threadIdx.x;
    const int row0 = blockIdx.x * 32;
    const int ty   = tid >> 4;
    const int tx   = tid & 15;

    float acc[2][6];
#pragma unroll
    for (int i = 0; i < 2; i++)
#pragma unroll
        for (int j = 0; j < 6; j++) acc[i][j] = 0.f;

    for (int kt = 0; kt < DMODEL; kt += 64) {
#pragma unroll
        for (int i = 0; i < 2; i++) {
            int e  = i * 256 + tid;
            int r  = e >> 4;
            int k4 = e & 15;
            float4 v = *(const float4*)&x[(size_t)(row0 + r) * DMODEL + kt + k4 * 4];
            As[k4 * 4 + 0][r] = v.x;
            As[k4 * 4 + 1][r] = v.y;
            As[k4 * 4 + 2][r] = v.z;
            As[k4 * 4 + 3][r] = v.w;
        }
#pragma unroll
        for (int i = 0; i < 6; i++) {
            int e  = i * 256 + tid;
            int c  = e >> 4;
            int k4 = e & 15;
            float4 v = *(const float4*)&g_wp[(size_t)c * DMODEL + kt + k4 * 4];
            Ws[k4 * 4 + 0][c] = v.x;
            Ws[k4 * 4 + 1][c] = v.y;
            Ws[k4 * 4 + 2][c] = v.z;
            Ws[k4 * 4 + 3][c] = v.w;
        }
        __syncthreads();

#pragma unroll 16
        for (int k = 0; k < 64; k++) {
            float a0 = As[k][ty * 2 + 0];
            float a1 = As[k][ty * 2 + 1];
            float wv[6];
#pragma unroll
            for (int j = 0; j < 6; j++) wv[j] = Ws[k][tx * 6 + j];
#pragma unroll
            for (int j = 0; j < 6; j++) {
                acc[0][j] = fmaf(a0, wv[j], acc[0][j]);
                acc[1][j] = fmaf(a1, wv[j], acc[1][j]);
            }
        }
        __syncthreads();
    }

#pragma unroll
    for (int i = 0; i < 2; i++) {
        int r = row0 + ty * 2 + i;
#pragma unroll
        for (int j = 0; j < 6; j++) {
            int c = tx * 6 + j;
            float v = acc[i][j];
            if (c < DTRANK)                 g_dp[(size_t)r * DTRANK + c] = v;
            else if (c < DTRANK + DSTATE)   g_bp[(size_t)r * DSTATE + (c - DTRANK)] = v;
            else                            g_cp[(size_t)r * DSTATE + (c - DTRANK - DSTATE)] = v;
        }
    }
}

// ---------------------------------------------------------------------------
// K2: delta = softplus(dp @ dtw^T + dtb); g_dd[b][l][d] = (delta, delta*u)
//   BM=32, BN=128, K=64, 256 threads, grid (128, 8)
// ---------------------------------------------------------------------------
__global__ __launch_bounds__(256)
void gemm2_kernel(const float* __restrict__ x,
                  const float* __restrict__ dtw,
                  const float* __restrict__ dtb,
                  const float* __restrict__ te)
{
    __shared__ float dps[64][33];
    __shared__ float ws [64][132];

    const int tid  = threadIdx.x;
    const int row0 = blockIdx.x * 32;
    const int col0 = blockIdx.y * 128;
    const int ty   = tid >> 4;
    const int tx   = tid & 15;

#pragma unroll
    for (int i = 0; i < 2; i++) {
        int e  = i * 256 + tid;
        int r  = e >> 4;
        int k4 = e & 15;
        float4 v = *(const float4*)&g_dp[(size_t)(row0 + r) * DTRANK + k4 * 4];
        dps[k4 * 4 + 0][r] = v.x;
        dps[k4 * 4 + 1][r] = v.y;
        dps[k4 * 4 + 2][r] = v.z;
        dps[k4 * 4 + 3][r] = v.w;
    }
#pragma unroll
    for (int i = 0; i < 8; i++) {
        int e  = i * 256 + tid;
        int c  = e >> 4;
        int k4 = e & 15;
        float4 v = *(const float4*)&dtw[(size_t)(col0 + c) * DTRANK + k4 * 4];
        ws[k4 * 4 + 0][c] = v.x;
        ws[k4 * 4 + 1][c] = v.y;
        ws[k4 * 4 + 2][c] = v.z;
        ws[k4 * 4 + 3][c] = v.w;
    }
    __syncthreads();

    float acc[2][8];
#pragma unroll
    for (int i = 0; i < 2; i++)
#pragma unroll
        for (int j = 0; j < 8; j++) acc[i][j] = 0.f;

#pragma unroll 16
    for (int k = 0; k < 64; k++) {
        float a0 = dps[k][ty * 2 + 0];
        float a1 = dps[k][ty * 2 + 1];
        float4 w0 = *(const float4*)&ws[k][tx * 8];
        float4 w1 = *(const float4*)&ws[k][tx * 8 + 4];
        float wv[8] = {w0.x, w0.y, w0.z, w0.w, w1.x, w1.y, w1.z, w1.w};
#pragma unroll
        for (int j = 0; j < 8; j++) {
            acc[0][j] = fmaf(a0, wv[j], acc[0][j]);
            acc[1][j] = fmaf(a1, wv[j], acc[1][j]);
        }
    }

#pragma unroll
    for (int i = 0; i < 2; i++) {
        int r  = row0 + ty * 2 + i;
        int c0 = col0 + tx * 8;
        float4 x0 = *(const float4*)&x[(size_t)r * DMODEL + c0];
        float4 x1 = *(const float4*)&x[(size_t)r * DMODEL + c0 + 4];
        float xv[8] = {x0.x, x0.y, x0.z, x0.w, x1.x, x1.y, x1.z, x1.w};
        float dl[8], du[8];
#pragma unroll
        for (int j = 0; j < 8; j++) {
            int c = c0 + j;
            float sg = 1.f / (1.f + __expf(-te[c]));
            float u  = xv[j] * sg;
            float v  = acc[i][j] + dtb[c];
            float delta = fmaxf(v, 0.f) + log1pf(__expf(-fabsf(v)));
            dl[j] = delta;
            du[j] = delta * u;
        }
        float4* dst = (float4*)&g_dd[(size_t)r * DMODEL + c0];
#pragma unroll
        for (int j = 0; j < 4; j++)
            dst[j] = make_float4(dl[2*j], du[2*j], dl[2*j+1], du[2*j+1]);
    }
}

// ---------------------------------------------------------------------------
// K3 (pass A): thread = (b, d, chunk), 16 states in regs, explicit MLP=8.
//   grid = 2 * 4 * 64 = 512 blocks, 256 threads.
// ---------------------------------------------------------------------------
__global__ __launch_bounds__(256)
void scanA_kernel()
{
    __shared__ float Bs[CLEN][DSTATE];   // 2KB

    const int tid   = threadIdx.x;
    const int blk   = blockIdx.x;
    const int b     = blk >> 8;
    const int rem   = blk & 255;
    const int dgrp  = rem >> 6;
    const int chunk = rem & 63;
    const int d     = dgrp * 256 + tid;
    const int ch    = b * DMODEL + d;
    const int gid   = ch * NCHUNK + chunk;
    const int l0    = chunk * CLEN;

    if (tid < CLEN * DSTATE / 4) {
        const float4* src = (const float4*)&g_bp[((size_t)b * SEQLEN + l0) * DSTATE];
        ((float4*)Bs)[tid] = src[tid];
    }

    float A[DSTATE];
#pragma unroll
    for (int n = 0; n < DSTATE; n++) A[n] = g_A[(size_t)d * DSTATE + n];
    bool uniform = true;
#pragma unroll
    for (int n = 1; n < DSTATE; n++) uniform &= (A[n] == A[0]);

    float h[DSTATE];
#pragma unroll
    for (int n = 0; n < DSTATE; n++) h[n] = 0.f;
    float T = 0.f;

    const float2* __restrict__ dd = g_dd + ((size_t)b * SEQLEN + l0) * DMODEL + d;
    __syncthreads();

    if (uniform) {
        const float A0 = A[0];
        for (int lb = 0; lb < CLEN / 8; lb++) {
            float2 t[8];
#pragma unroll
            for (int i = 0; i < 8; i++) t[i] = dd[(size_t)(lb * 8 + i) * DMODEL];
            float a[8];
#pragma unroll
            for (int i = 0; i < 8; i++) { a[i] = __expf(t[i].x * A0); T += t[i].x; }
#pragma unroll
            for (int i = 0; i < 8; i++) {
                int l = lb * 8 + i;
#pragma unroll
                for (int n = 0; n < DSTATE; n++)
                    h[n] = fmaf(a[i], h[n], t[i].y * Bs[l][n]);
            }
        }
    } else {
        for (int lb = 0; lb < CLEN / 8; lb++) {
            float2 t[8];
#pragma unroll
            for (int i = 0; i < 8; i++) t[i] = dd[(size_t)(lb * 8 + i) * DMODEL];
#pragma unroll
            for (int i = 0; i < 8; i++) {
                int l = lb * 8 + i;
                T += t[i].x;
#pragma unroll
                for (int n = 0; n < DSTATE; n++)
                    h[n] = fmaf(__expf(t[i].x * A[n]), h[n], t[i].y * Bs[l][n]);
            }
        }
    }

#pragma unroll
    for (int n = 0; n < DSTATE; n++) g_hl[(size_t)gid * DSTATE + n] = h[n];
    g_T[gid] = T;
}

// ---------------------------------------------------------------------------
// K4 (pass B): chunk combine per (channel, n) with FORCED MLP=8 batches.
// ---------------------------------------------------------------------------
__global__ __launch_bounds__(256)
void scanB_kernel()
{
    const int idx = blockIdx.x * 256 + threadIdx.x;   // 32768
    const int ch  = idx >> 4;
    const int n   = idx & 15;
    const int d   = ch & (DMODEL - 1);

    const float A = g_A[(size_t)d * DSTATE + n];

    const float* __restrict__ hlp = g_hl  + (size_t)ch * NCHUNK * DSTATE + n;
    const float* __restrict__ Tp  = g_T   + (size_t)ch * NCHUNK;
    float*       __restrict__ hip = g_hin + (size_t)ch * NCHUNK * DSTATE + n;

    float hin = 0.f;
    for (int gblk = 0; gblk < NCHUNK / 8; gblk++) {
        float hl8[8], a8[8];
#pragma unroll
        for (int i = 0; i < 8; i++) hl8[i] = hlp[(size_t)(gblk * 8 + i) * DSTATE];
#pragma unroll
        for (int i = 0; i < 8; i++) a8[i]  = __expf(Tp[gblk * 8 + i] * A);
#pragma unroll
        for (int i = 0; i < 8; i++) {
            hip[(size_t)(gblk * 8 + i) * DSTATE] = hin;
            hin = fmaf(hin, a8[i], hl8[i]);
        }
    }
}

// ---------------------------------------------------------------------------
// K5 (pass C): full re-scan with correct h0; coalesced output, MLP=8.
// ---------------------------------------------------------------------------
__global__ __launch_bounds__(256)
void scanC_kernel(const float* __restrict__ x,
                  const float* __restrict__ te,
                  const float* __restrict__ Dp,
                  float* __restrict__ out)
{
    __shared__ float Bs[CLEN][DSTATE];
    __shared__ float Cs[CLEN][DSTATE];

    const int tid   = threadIdx.x;
    const int blk   = blockIdx.x;
    const int b     = blk >> 8;
    const int rem   = blk & 255;
    const int dgrp  = rem >> 6;
    const int chunk = rem & 63;
    const int d     = dgrp * 256 + tid;
    const int ch    = b * DMODEL + d;
    const int gid   = ch * NCHUNK + chunk;
    const int l0    = chunk * CLEN;

    if (tid < CLEN * DSTATE / 4) {
        const float4* sb = (const float4*)&g_bp[((size_t)b * SEQLEN + l0) * DSTATE];
        ((float4*)Bs)[tid] = sb[tid];
    } else if (tid < CLEN * DSTATE / 2) {
        const float4* sc = (const float4*)&g_cp[((size_t)b * SEQLEN + l0) * DSTATE];
        ((float4*)Cs)[tid - CLEN * DSTATE / 4] = sc[tid - CLEN * DSTATE / 4];
    }

    float A[DSTATE];
#pragma unroll
    for (int n = 0; n < DSTATE; n++) A[n] = g_A[(size_t)d * DSTATE + n];
    bool uniform = true;
#pragma unroll
    for (int n = 1; n < DSTATE; n++) uniform &= (A[n] == A[0]);

    float h[DSTATE];
#pragma unroll
    for (int n = 0; n < DSTATE; n++) h[n] = g_hin[(size_t)gid * DSTATE + n];

    const float sgD = (1.f / (1.f + __expf(-te[d]))) * Dp[d];

    const float2* __restrict__ dd = g_dd + ((size_t)b * SEQLEN + l0) * DMODEL + d;
    const float*  __restrict__ xp = x    + ((size_t)b * SEQLEN + l0) * DMODEL + d;
    float*        __restrict__ op = out  + ((size_t)b * SEQLEN + l0) * DMODEL + d;
    __syncthreads();

    if (uniform) {
        const float A0 = A[0];
        for (int lb = 0; lb < CLEN / 8; lb++) {
            float2 t[8];
            float  xv[8];
#pragma unroll
            for (int i = 0; i < 8; i++) t[i]  = dd[(size_t)(lb * 8 + i) * DMODEL];
#pragma unroll
            for (int i = 0; i < 8; i++) xv[i] = xp[(size_t)(lb * 8 + i) * DMODEL];
            float a[8];
#pragma unroll
            for (int i = 0; i < 8; i++) a[i] = __expf(t[i].x * A0);
#pragma unroll
            for (int i = 0; i < 8; i++) {
                int l = lb * 8 + i;
                float y = 0.f;
#pragma unroll
                for (int n = 0; n < DSTATE; n++) {
                    h[n] = fmaf(a[i], h[n], t[i].y * Bs[l][n]);
                    y    = fmaf(h[n], Cs[l][n], y);
                }
                op[(size_t)l * DMODEL] = fmaf(xv[i], sgD, y);
            }
        }
    } else {
        for (int lb = 0; lb < CLEN / 8; lb++) {
            float2 t[8];
            float  xv[8];
#pragma unroll
            for (int i = 0; i < 8; i++) t[i]  = dd[(size_t)(lb * 8 + i) * DMODEL];
#pragma unroll
            for (int i = 0; i < 8; i++) xv[i] = xp[(size_t)(lb * 8 + i) * DMODEL];
#pragma unroll
            for (int i = 0; i < 8; i++) {
                int l = lb * 8 + i;
                float y = 0.f;
#pragma unroll
                for (int n = 0; n < DSTATE; n++) {
                    h[n] = fmaf(__expf(t[i].x * A[n]), h[n], t[i].y * Bs[l][n]);
                    y    = fmaf(h[n], Cs[l][n], y);
                }
                op[(size_t)l * DMODEL] = fmaf(xv[i], sgD, y);
            }
        }
    }
}

// ---------------------------------------------------------------------------
// Launch
// ---------------------------------------------------------------------------
extern "C" void kernel_launch(void* const* d_in, const int* in_sizes, int n_in,
                              void* d_out, int out_size)
{
    const float* x    = (const float*)d_in[0];
    const float* Alog = (const float*)d_in[1];
    const float* xpw  = (const float*)d_in[2];
    const float* dtw  = (const float*)d_in[3];
    const float* dtb  = (const float*)d_in[4];
    const float* Dp   = (const float*)d_in[5];
    const float* te   = (const float*)d_in[6];
    float* out = (float*)d_out;

    prep_kernel <<<(96 * DMODEL + 255) / 256, 256>>>(xpw, te, Alog);
    gemm1_kernel<<<NROWS / 32, 256>>>(x);
    gemm2_kernel<<<dim3(NROWS / 32, DMODEL / 128), 256>>>(x, dtw, dtb, te);
    scanA_kernel<<<BATCH * 4 * NCHUNK, 256>>>();
    scanB_kernel<<<(NCH * DSTATE) / 256, 256>>>();
    scanC_kernel<<<BATCH * 4 * NCHUNK, 256>>>(x, te, Dp, out);
}

// round 6
// speedup vs baseline: 1.7557x; 1.0540x over previous
#include <cuda_runtime.h>
#include <cuda_bf16.h>
#include <cstdint>

#define BATCH   2
#define SEQLEN  2048
#define DMODEL  1024
#define DSTATE  16
#define DTRANK  64
#define NROWS   (BATCH * SEQLEN)          // 4096
#define NCHUNK  64
#define CLEN    (SEQLEN / NCHUNK)         // 32
#define NCH     (BATCH * DMODEL)          // 2048
#define NGRP    (NCH * NCHUNK)            // 131072
#define KSPLIT  4

typedef unsigned long long ull;

// ---------------------------------------------------------------------------
// f32x2 packed-math helpers (bit-exact IEEE fp32 per lane)
// ---------------------------------------------------------------------------
__device__ __forceinline__ ull pack2(float lo, float hi) {
    ull r; asm("mov.b64 %0, {%1, %2};" : "=l"(r) : "f"(lo), "f"(hi)); return r;
}
__device__ __forceinline__ void unpack2(ull v, float& lo, float& hi) {
    asm("mov.b64 {%0, %1}, %2;" : "=f"(lo), "=f"(hi) : "l"(v));
}
__device__ __forceinline__ ull fma2(ull a, ull b, ull c) {
    ull d; asm("fma.rn.f32x2 %0, %1, %2, %3;" : "=l"(d) : "l"(a), "l"(b), "l"(c)); return d;
}
__device__ __forceinline__ ull mul2(ull a, ull b) {
    ull d; asm("mul.rn.f32x2 %0, %1, %2;" : "=l"(d) : "l"(a), "l"(b)); return d;
}

// ---------------------------------------------------------------------------
// Device scratch
// ---------------------------------------------------------------------------
__device__ float  g_wp [96 * DMODEL];                          // W * sig(te)
__device__ float  g_A  [DMODEL * DSTATE];                      // -exp(A_log)
__device__ float  g_dpp[(size_t)KSPLIT * NROWS * DTRANK];      // dp partials
__device__ float  g_bcp[(size_t)KSPLIT * NROWS * 32];          // B|C partials
__device__ float  g_bp [(size_t)NROWS * DSTATE];               // B plane (summed)
__device__ float  g_cp [(size_t)NROWS * DSTATE];               // C plane (summed)
__device__ float2 g_dd [(size_t)NROWS * DMODEL];               // (delta, delta*u)
__device__ float  g_hl [(size_t)NGRP * DSTATE];                // chunk-local states
__device__ float  g_T  [(size_t)NGRP];                         // chunk delta sums
__device__ float  g_hin[(size_t)NGRP * DSTATE];                // chunk incoming states

// ---------------------------------------------------------------------------
// K0: fold sigmoid(trend) into x_proj_w; precompute A = -exp(A_log)
// ---------------------------------------------------------------------------
__global__ __launch_bounds__(256)
void prep_kernel(const float* __restrict__ W, const float* __restrict__ te,
                 const float* __restrict__ A_log)
{
    int idx = blockIdx.x * 256 + threadIdx.x;
    if (idx < 96 * DMODEL) {
        int k = idx & (DMODEL - 1);
        float sg = 1.f / (1.f + __expf(-te[k]));
        g_wp[idx] = W[idx] * sg;
    }
    if (idx < DMODEL * DSTATE) {
        g_A[idx] = -__expf(A_log[idx]);
    }
}

// ---------------------------------------------------------------------------
// K1: split-K GEMM1 partials.  xz_part = x[:, kr] @ wp[:, kr]^T
//   grid (128 rowblocks, 4 ksplits), 256 thr. BM=32, BN=96, f32x2 col-pairs.
// ---------------------------------------------------------------------------
__global__ __launch_bounds__(256)
void gemm1_kernel(const float* __restrict__ x)
{
    __shared__ float As[64][34];
    __shared__ float Ws[64][98];

    const int tid  = threadIdx.x;
    const int row0 = blockIdx.x * 32;
    const int ks   = blockIdx.y;
    const int ty   = tid >> 4;         // 0..15 -> rows ty*2..+1
    const int tx   = tid & 15;         // 0..15 -> cols tx*6..+5

    ull accp[2][3];
#pragma unroll
    for (int i = 0; i < 2; i++)
#pragma unroll
        for (int j = 0; j < 3; j++) accp[i][j] = 0ull;

    for (int kk = 0; kk < 256; kk += 64) {
        const int kt = ks * 256 + kk;
#pragma unroll
        for (int i = 0; i < 2; i++) {
            int e  = i * 256 + tid;
            int r  = e >> 4;
            int k4 = e & 15;
            float4 v = *(const float4*)&x[(size_t)(row0 + r) * DMODEL + kt + k4 * 4];
            As[k4 * 4 + 0][r] = v.x;
            As[k4 * 4 + 1][r] = v.y;
            As[k4 * 4 + 2][r] = v.z;
            As[k4 * 4 + 3][r] = v.w;
        }
#pragma unroll
        for (int i = 0; i < 6; i++) {
            int e  = i * 256 + tid;
            int c  = e >> 4;
            int k4 = e & 15;
            float4 v = *(const float4*)&g_wp[(size_t)c * DMODEL + kt + k4 * 4];
            Ws[k4 * 4 + 0][c] = v.x;
            Ws[k4 * 4 + 1][c] = v.y;
            Ws[k4 * 4 + 2][c] = v.z;
            Ws[k4 * 4 + 3][c] = v.w;
        }
        __syncthreads();

#pragma unroll 16
        for (int k = 0; k < 64; k++) {
            float a0 = As[k][ty * 2 + 0];
            float a1 = As[k][ty * 2 + 1];
            ull a0p = pack2(a0, a0);
            ull a1p = pack2(a1, a1);
            ull wp0 = *(const ull*)&Ws[k][tx * 6 + 0];
            ull wp1 = *(const ull*)&Ws[k][tx * 6 + 2];
            ull wp2 = *(const ull*)&Ws[k][tx * 6 + 4];
            accp[0][0] = fma2(a0p, wp0, accp[0][0]);
            accp[0][1] = fma2(a0p, wp1, accp[0][1]);
            accp[0][2] = fma2(a0p, wp2, accp[0][2]);
            accp[1][0] = fma2(a1p, wp0, accp[1][0]);
            accp[1][1] = fma2(a1p, wp1, accp[1][1]);
            accp[1][2] = fma2(a1p, wp2, accp[1][2]);
        }
        __syncthreads();
    }

#pragma unroll
    for (int i = 0; i < 2; i++) {
        int r = row0 + ty * 2 + i;
#pragma unroll
        for (int jp = 0; jp < 3; jp++) {
            float v0, v1;
            unpack2(accp[i][jp], v0, v1);
            int c = tx * 6 + jp * 2;
#pragma unroll
            for (int h = 0; h < 2; h++) {
                float v = h ? v1 : v0;
                int cc = c + h;
                if (cc < DTRANK)
                    g_dpp[((size_t)ks * NROWS + r) * DTRANK + cc] = v;
                else
                    g_bcp[((size_t)ks * NROWS + r) * 32 + (cc - DTRANK)] = v;
            }
        }
    }
}

// ---------------------------------------------------------------------------
// K2 (fused GEMM2 + chunk-local scan):
//   block (lb, dt): rows r0=lb*32 (one chunk), cols dt*128.
//   A) sum dp/bc partials (dp->smem k-major, B->smem, y==0 writes bp/cp)
//   B) f32x2 GEMM: delta_acc = dp @ dtw_tile^T
//   C) softplus + u; write g_dd; stage delta/du in smem
//   D) chunk-local scan: 256 thr = 128 d x 2 state-halves -> g_hl, g_T
// ---------------------------------------------------------------------------
__global__ __launch_bounds__(256)
void gemm2s_kernel(const float* __restrict__ x,
                   const float* __restrict__ dtw,
                   const float* __restrict__ dtb,
                   const float* __restrict__ te)
{
    __shared__ __align__(16) char smraw[44544];
    float (*dps)[34]    = (float(*)[34])  (smraw);               // 8704 B
    float (*ws)[132]    = (float(*)[132]) (smraw + 8704);        // 33792 B
    float (*sdelta)[132]= (float(*)[132]) (smraw + 8704);        // union w/ ws
    float (*sdu)[132]   = (float(*)[132]) (smraw + 8704 + 16896);
    float (*Bs)[16]     = (float(*)[16])  (smraw + 42496);       // 2048 B

    const int tid  = threadIdx.x;
    const int row0 = blockIdx.x * 32;
    const int by   = blockIdx.y;
    const int ty   = tid >> 4;
    const int tx   = tid & 15;

    // ---- Phase A: sum partials ----
#pragma unroll
    for (int i = 0; i < 2; i++) {
        int e  = i * 256 + tid;
        int r  = e >> 4;
        int k4 = e & 15;
        float4 s = make_float4(0.f, 0.f, 0.f, 0.f);
#pragma unroll
        for (int ks = 0; ks < KSPLIT; ks++) {
            float4 v = *(const float4*)&g_dpp[((size_t)ks * NROWS + row0 + r) * DTRANK + k4 * 4];
            s.x += v.x; s.y += v.y; s.z += v.z; s.w += v.w;
        }
        dps[k4 * 4 + 0][r] = s.x;
        dps[k4 * 4 + 1][r] = s.y;
        dps[k4 * 4 + 2][r] = s.z;
        dps[k4 * 4 + 3][r] = s.w;
    }
    {
        int r  = tid >> 3;
        int c4 = tid & 7;
        float4 s = make_float4(0.f, 0.f, 0.f, 0.f);
#pragma unroll
        for (int ks = 0; ks < KSPLIT; ks++) {
            float4 v = *(const float4*)&g_bcp[((size_t)ks * NROWS + row0 + r) * 32 + c4 * 4];
            s.x += v.x; s.y += v.y; s.z += v.z; s.w += v.w;
        }
        if (c4 < 4) {
            *(float4*)&Bs[r][c4 * 4] = s;
            if (by == 0) *(float4*)&g_bp[(size_t)(row0 + r) * DSTATE + c4 * 4] = s;
        } else if (by == 0) {
            *(float4*)&g_cp[(size_t)(row0 + r) * DSTATE + (c4 - 4) * 4] = s;
        }
    }
    // ---- load dtw tile ----
#pragma unroll
    for (int i = 0; i < 8; i++) {
        int e  = i * 256 + tid;
        int c  = e >> 4;
        int k4 = e & 15;
        float4 v = *(const float4*)&dtw[(size_t)(by * 128 + c) * DTRANK + k4 * 4];
        ws[k4 * 4 + 0][c] = v.x;
        ws[k4 * 4 + 1][c] = v.y;
        ws[k4 * 4 + 2][c] = v.z;
        ws[k4 * 4 + 3][c] = v.w;
    }
    __syncthreads();

    // ---- Phase B: f32x2 GEMM ----
    ull accp[2][4];
#pragma unroll
    for (int i = 0; i < 2; i++)
#pragma unroll
        for (int j = 0; j < 4; j++) accp[i][j] = 0ull;

#pragma unroll 16
    for (int k = 0; k < 64; k++) {
        float a0 = dps[k][ty * 2 + 0];
        float a1 = dps[k][ty * 2 + 1];
        ull a0p = pack2(a0, a0);
        ull a1p = pack2(a1, a1);
#pragma unroll
        for (int jp = 0; jp < 4; jp++) {
            ull wpv = *(const ull*)&ws[k][tx * 8 + jp * 2];
            accp[0][jp] = fma2(a0p, wpv, accp[0][jp]);
            accp[1][jp] = fma2(a1p, wpv, accp[1][jp]);
        }
    }
    __syncthreads();   // done reading ws; region becomes sdelta/sdu

    // ---- Phase C: epilogue ----
#pragma unroll
    for (int i = 0; i < 2; i++) {
        int lloc = ty * 2 + i;
        int r    = row0 + lloc;
        int c0   = by * 128 + tx * 8;
        float4 x0 = *(const float4*)&x[(size_t)r * DMODEL + c0];
        float4 x1 = *(const float4*)&x[(size_t)r * DMODEL + c0 + 4];
        float xv[8] = {x0.x, x0.y, x0.z, x0.w, x1.x, x1.y, x1.z, x1.w};
        float dl[8], du[8];
#pragma unroll
        for (int jp = 0; jp < 4; jp++) {
            float v0, v1;
            unpack2(accp[i][jp], v0, v1);
            float av[2] = {v0, v1};
#pragma unroll
            for (int h = 0; h < 2; h++) {
                int j = jp * 2 + h;
                int c = c0 + j;
                float sg = 1.f / (1.f + __expf(-te[c]));
                float u  = xv[j] * sg;
                float v  = av[h] + dtb[c];
                float delta = fmaxf(v, 0.f) + log1pf(__expf(-fabsf(v)));
                dl[j] = delta;
                du[j] = delta * u;
            }
        }
        float4* dst = (float4*)&g_dd[(size_t)r * DMODEL + c0];
#pragma unroll
        for (int j = 0; j < 4; j++)
            dst[j] = make_float4(dl[2*j], du[2*j], dl[2*j+1], du[2*j+1]);
        *(float4*)&sdelta[lloc][tx * 8]     = make_float4(dl[0], dl[1], dl[2], dl[3]);
        *(float4*)&sdelta[lloc][tx * 8 + 4] = make_float4(dl[4], dl[5], dl[6], dl[7]);
        *(float4*)&sdu[lloc][tx * 8]        = make_float4(du[0], du[1], du[2], du[3]);
        *(float4*)&sdu[lloc][tx * 8 + 4]    = make_float4(du[4], du[5], du[6], du[7]);
    }
    __syncthreads();

    // ---- Phase D: chunk-local scan ----
    {
        const int dloc = tid & 127;
        const int nh   = tid >> 7;              // state half: 0 -> n 0..7, 1 -> 8..15
        const int b    = row0 >> 11;
        const int chunk= (row0 >> 5) & (NCHUNK - 1);
        const int d    = by * 128 + dloc;
        const int gid  = (b * DMODEL + d) * NCHUNK + chunk;

        float A[8];
#pragma unroll
        for (int j = 0; j < 8; j++) A[j] = g_A[(size_t)d * DSTATE + nh * 8 + j];
        bool uniform = true;
#pragma unroll
        for (int j = 1; j < 8; j++) uniform &= (A[j] == A[0]);

        ull hp[4] = {0ull, 0ull, 0ull, 0ull};
        float T = 0.f;

        if (uniform) {
            const float A0 = A[0];
#pragma unroll 4
            for (int l = 0; l < CLEN; l++) {
                float dx = sdelta[l][dloc];
                float dv = sdu[l][dloc];
                T += dx;
                float a = __expf(dx * A0);
                ull ap  = pack2(a, a);
                ull dup = pack2(dv, dv);
#pragma unroll
                for (int p = 0; p < 4; p++) {
                    ull bpr = *(const ull*)&Bs[l][nh * 8 + p * 2];
                    hp[p] = fma2(ap, hp[p], mul2(dup, bpr));
                }
            }
        } else {
#pragma unroll 2
            for (int l = 0; l < CLEN; l++) {
                float dx = sdelta[l][dloc];
                float dv = sdu[l][dloc];
                T += dx;
                ull dup = pack2(dv, dv);
#pragma unroll
                for (int p = 0; p < 4; p++) {
                    ull ap  = pack2(__expf(dx * A[p*2]), __expf(dx * A[p*2+1]));
                    ull bpr = *(const ull*)&Bs[l][nh * 8 + p * 2];
                    hp[p] = fma2(ap, hp[p], mul2(dup, bpr));
                }
            }
        }
#pragma unroll
        for (int p = 0; p < 4; p++)
            *(ull*)&g_hl[(size_t)gid * DSTATE + nh * 8 + p * 2] = hp[p];
        if (nh == 0) g_T[gid] = T;
    }
}

// ---------------------------------------------------------------------------
// K3 (pass B): chunk combine per (channel, n), forced MLP=8 batches.
// ---------------------------------------------------------------------------
__global__ __launch_bounds__(256)
void scanB_kernel()
{
    const int idx = blockIdx.x * 256 + threadIdx.x;   // 32768
    const int ch  = idx >> 4;
    const int n   = idx & 15;
    const int d   = ch & (DMODEL - 1);

    const float A = g_A[(size_t)d * DSTATE + n];

    const float* __restrict__ hlp = g_hl  + (size_t)ch * NCHUNK * DSTATE + n;
    const float* __restrict__ Tp  = g_T   + (size_t)ch * NCHUNK;
    float*       __restrict__ hip = g_hin + (size_t)ch * NCHUNK * DSTATE + n;

    float hin = 0.f;
    for (int gblk = 0; gblk < NCHUNK / 8; gblk++) {
        float hl8[8], a8[8];
#pragma unroll
        for (int i = 0; i < 8; i++) hl8[i] = hlp[(size_t)(gblk * 8 + i) * DSTATE];
#pragma unroll
        for (int i = 0; i < 8; i++) a8[i]  = __expf(Tp[gblk * 8 + i] * A);
#pragma unroll
        for (int i = 0; i < 8; i++) {
            hip[(size_t)(gblk * 8 + i) * DSTATE] = hin;
            hin = fmaf(hin, a8[i], hl8[i]);
        }
    }
}

// ---------------------------------------------------------------------------
// K4 (pass C): full re-scan with correct h0; f32x2 packed states; MLP=8.
// ---------------------------------------------------------------------------
__global__ __launch_bounds__(256)
void scanC_kernel(const float* __restrict__ x,
                  const float* __restrict__ te,
                  const float* __restrict__ Dp,
                  float* __restrict__ out)
{
    __shared__ float Bs[CLEN][DSTATE];
    __shared__ float Cs[CLEN][DSTATE];

    const int tid   = threadIdx.x;
    const int blk   = blockIdx.x;
    const int b     = blk >> 8;
    const int rem   = blk & 255;
    const int dgrp  = rem >> 6;
    const int chunk = rem & 63;
    const int d     = dgrp * 256 + tid;
    const int ch    = b * DMODEL + d;
    const int gid   = ch * NCHUNK + chunk;
    const int l0    = chunk * CLEN;

    if (tid < CLEN * DSTATE / 4) {
        const float4* sb = (const float4*)&g_bp[((size_t)b * SEQLEN + l0) * DSTATE];
        ((float4*)Bs)[tid] = sb[tid];
    } else if (tid < CLEN * DSTATE / 2) {
        const float4* sc = (const float4*)&g_cp[((size_t)b * SEQLEN + l0) * DSTATE];
        ((float4*)Cs)[tid - CLEN * DSTATE / 4] = sc[tid - CLEN * DSTATE / 4];
    }

    float A[DSTATE];
#pragma unroll
    for (int n = 0; n < DSTATE; n++) A[n] = g_A[(size_t)d * DSTATE + n];
    bool uniform = true;
#pragma unroll
    for (int n = 1; n < DSTATE; n++) uniform &= (A[n] == A[0]);

    ull hp[8];
#pragma unroll
    for (int p = 0; p < 8; p++)
        hp[p] = *(const ull*)&g_hin[(size_t)gid * DSTATE + p * 2];

    const float sgD = (1.f / (1.f + __expf(-te[d]))) * Dp[d];

    const float2* __restrict__ dd = g_dd + ((size_t)b * SEQLEN + l0) * DMODEL + d;
    const float*  __restrict__ xp = x    + ((size_t)b * SEQLEN + l0) * DMODEL + d;
    float*        __restrict__ op = out  + ((size_t)b * SEQLEN + l0) * DMODEL + d;
    __syncthreads();

    if (uniform) {
        const float A0 = A[0];
        for (int lb = 0; lb < CLEN / 8; lb++) {
            float2 t[8];
            float  xv[8];
#pragma unroll
            for (int i = 0; i < 8; i++) t[i]  = dd[(size_t)(lb * 8 + i) * DMODEL];
#pragma unroll
            for (int i = 0; i < 8; i++) xv[i] = xp[(size_t)(lb * 8 + i) * DMODEL];
            float a[8];
#pragma unroll
            for (int i = 0; i < 8; i++) a[i] = __expf(t[i].x * A0);
#pragma unroll
            for (int i = 0; i < 8; i++) {
                int l = lb * 8 + i;
                ull ap  = pack2(a[i], a[i]);
                ull dup = pack2(t[i].y, t[i].y);
                ull yp  = 0ull;
#pragma unroll
                for (int p = 0; p < 8; p++) {
                    ull bpr = *(const ull*)&Bs[l][p * 2];
                    ull cpr = *(const ull*)&Cs[l][p * 2];
                    hp[p] = fma2(ap, hp[p], mul2(dup, bpr));
                    yp    = fma2(hp[p], cpr, yp);
                }
                float ylo, yhi;
                unpack2(yp, ylo, yhi);
                op[(size_t)l * DMODEL] = fmaf(xv[i], sgD, ylo + yhi);
            }
        }
    } else {
        for (int lb = 0; lb < CLEN / 8; lb++) {
            float2 t[8];
            float  xv[8];
#pragma unroll
            for (int i = 0; i < 8; i++) t[i]  = dd[(size_t)(lb * 8 + i) * DMODEL];
#pragma unroll
            for (int i = 0; i < 8; i++) xv[i] = xp[(size_t)(lb * 8 + i) * DMODEL];
#pragma unroll
            for (int i = 0; i < 8; i++) {
                int l = lb * 8 + i;
                ull dup = pack2(t[i].y, t[i].y);
                ull yp  = 0ull;
#pragma unroll
                for (int p = 0; p < 8; p++) {
                    ull ap  = pack2(__expf(t[i].x * A[p*2]), __expf(t[i].x * A[p*2+1]));
                    ull bpr = *(const ull*)&Bs[l][p * 2];
                    ull cpr = *(const ull*)&Cs[l][p * 2];
                    hp[p] = fma2(ap, hp[p], mul2(dup, bpr));
                    yp    = fma2(hp[p], cpr, yp);
                }
                float ylo, yhi;
                unpack2(yp, ylo, yhi);
                op[(size_t)l * DMODEL] = fmaf(xv[i], sgD, ylo + yhi);
            }
        }
    }
}

// ---------------------------------------------------------------------------
// Launch
// ---------------------------------------------------------------------------
extern "C" void kernel_launch(void* const* d_in, const int* in_sizes, int n_in,
                              void* d_out, int out_size)
{
    const float* x    = (const float*)d_in[0];
    const float* Alog = (const float*)d_in[1];
    const float* xpw  = (const float*)d_in[2];
    const float* dtw  = (const float*)d_in[3];
    const float* dtb  = (const float*)d_in[4];
    const float* Dp   = (const float*)d_in[5];
    const float* te   = (const float*)d_in[6];
    float* out = (float*)d_out;

    prep_kernel  <<<(96 * DMODEL + 255) / 256, 256>>>(xpw, te, Alog);
    gemm1_kernel <<<dim3(NROWS / 32, KSPLIT), 256>>>(x);
    gemm2s_kernel<<<dim3(NROWS / 32, DMODEL / 128), 256>>>(x, dtw, dtb, te);
    scanB_kernel <<<(NCH * DSTATE) / 256, 256>>>();
    scanC_kernel <<<BATCH * 4 * NCHUNK, 256>>>(x, te, Dp, out);
}

// round 8
// speedup vs baseline: 2.1784x; 1.2408x over previous
#include <cuda_runtime.h>
#include <cuda_bf16.h>
#include <cstdint>

#define BATCH   2
#define SEQLEN  2048
#define DMODEL  1024
#define DSTATE  16
#define DTRANK  64
#define NROWS   (BATCH * SEQLEN)          // 4096
#define NCHUNK  64
#define CLEN    (SEQLEN / NCHUNK)         // 32
#define NCH     (BATCH * DMODEL)          // 2048
#define NGRP    (NCH * NCHUNK)            // 131072
#define KSPLIT  4

typedef unsigned long long ull;

// ---------------------------------------------------------------------------
// f32x2 packed-math helpers (bit-exact IEEE fp32 per lane)
// ---------------------------------------------------------------------------
__device__ __forceinline__ ull pack2(float lo, float hi) {
    ull r; asm("mov.b64 %0, {%1, %2};" : "=l"(r) : "f"(lo), "f"(hi)); return r;
}
__device__ __forceinline__ void unpack2(ull v, float& lo, float& hi) {
    asm("mov.b64 {%0, %1}, %2;" : "=f"(lo), "=f"(hi) : "l"(v));
}
__device__ __forceinline__ ull fma2(ull a, ull b, ull c) {
    ull d; asm("fma.rn.f32x2 %0, %1, %2, %3;" : "=l"(d) : "l"(a), "l"(b), "l"(c)); return d;
}
__device__ __forceinline__ ull mul2(ull a, ull b) {
    ull d; asm("mul.rn.f32x2 %0, %1, %2;" : "=l"(d) : "l"(a), "l"(b)); return d;
}

// ---------------------------------------------------------------------------
// Device scratch.  Boundary-state arrays are CHUNK-MAJOR: [chunk][ch][n]
// ---------------------------------------------------------------------------
__device__ float  g_wp [96 * DMODEL];                          // W * sig(te)
__device__ float  g_A  [DMODEL * DSTATE];                      // -exp(A_log)
__device__ float  g_dpp[(size_t)KSPLIT * NROWS * DTRANK];      // dp partials
__device__ float  g_bcp[(size_t)KSPLIT * NROWS * 32];          // B|C partials
__device__ float  g_bp [(size_t)NROWS * DSTATE];               // B plane (summed)
__device__ float  g_cp [(size_t)NROWS * DSTATE];               // C plane (summed)
__device__ float2 g_dd [(size_t)NROWS * DMODEL];               // (delta, delta*u)
__device__ float  g_hl [(size_t)NGRP * DSTATE];                // [chunk][ch][n]
__device__ float  g_T  [(size_t)NGRP];                         // [chunk][ch]
__device__ float  g_hin[(size_t)NGRP * DSTATE];                // [chunk][ch][n]

// ---------------------------------------------------------------------------
// K0: fold sigmoid(trend) into x_proj_w; precompute A = -exp(A_log)
// ---------------------------------------------------------------------------
__global__ __launch_bounds__(256)
void prep_kernel(const float* __restrict__ W, const float* __restrict__ te,
                 const float* __restrict__ A_log)
{
    int idx = blockIdx.x * 256 + threadIdx.x;
    if (idx < 96 * DMODEL) {
        int k = idx & (DMODEL - 1);
        float sg = 1.f / (1.f + __expf(-te[k]));
        g_wp[idx] = W[idx] * sg;
    }
    if (idx < DMODEL * DSTATE) {
        g_A[idx] = -__expf(A_log[idx]);
    }
}

// ---------------------------------------------------------------------------
// K1: split-K GEMM1 partials.  BM=64, BN=96, BK=64, 256 thr, tile 4x6 (f32x2)
//   grid (64 rowblocks, 4 ksplits)
// ---------------------------------------------------------------------------
__global__ __launch_bounds__(256)
void gemm1_kernel(const float* __restrict__ x)
{
    __shared__ float As[64][68];
    __shared__ float Ws[64][98];

    const int tid  = threadIdx.x;
    const int row0 = blockIdx.x * 64;
    const int ks   = blockIdx.y;
    const int ty   = tid >> 4;         // 0..15 -> rows ty*4..+3
    const int tx   = tid & 15;         // 0..15 -> cols tx*6..+5

    ull accp[4][3];
#pragma unroll
    for (int i = 0; i < 4; i++)
#pragma unroll
        for (int j = 0; j < 3; j++) accp[i][j] = 0ull;

    for (int kk = 0; kk < 256; kk += 64) {
        const int kt = ks * 256 + kk;
        // A tile: 64 rows x 64 k = 1024 float4, 4/thread
#pragma unroll
        for (int i = 0; i < 4; i++) {
            int e  = i * 256 + tid;
            int r  = e >> 4;
            int k4 = e & 15;
            float4 v = *(const float4*)&x[(size_t)(row0 + r) * DMODEL + kt + k4 * 4];
            As[k4 * 4 + 0][r] = v.x;
            As[k4 * 4 + 1][r] = v.y;
            As[k4 * 4 + 2][r] = v.z;
            As[k4 * 4 + 3][r] = v.w;
        }
        // W tile: 96 cols x 64 k = 1536 float4, 6/thread
#pragma unroll
        for (int i = 0; i < 6; i++) {
            int e  = i * 256 + tid;
            int c  = e >> 4;
            int k4 = e & 15;
            float4 v = *(const float4*)&g_wp[(size_t)c * DMODEL + kt + k4 * 4];
            Ws[k4 * 4 + 0][c] = v.x;
            Ws[k4 * 4 + 1][c] = v.y;
            Ws[k4 * 4 + 2][c] = v.z;
            Ws[k4 * 4 + 3][c] = v.w;
        }
        __syncthreads();

#pragma unroll 8
        for (int k = 0; k < 64; k++) {
            float4 a4 = *(const float4*)&As[k][ty * 4];
            ull ap[4];
            ap[0] = pack2(a4.x, a4.x);
            ap[1] = pack2(a4.y, a4.y);
            ap[2] = pack2(a4.z, a4.z);
            ap[3] = pack2(a4.w, a4.w);
            ull wp0 = *(const ull*)&Ws[k][tx * 6 + 0];
            ull wp1 = *(const ull*)&Ws[k][tx * 6 + 2];
            ull wp2 = *(const ull*)&Ws[k][tx * 6 + 4];
#pragma unroll
            for (int i = 0; i < 4; i++) {
                accp[i][0] = fma2(ap[i], wp0, accp[i][0]);
                accp[i][1] = fma2(ap[i], wp1, accp[i][1]);
                accp[i][2] = fma2(ap[i], wp2, accp[i][2]);
            }
        }
        __syncthreads();
    }

#pragma unroll
    for (int i = 0; i < 4; i++) {
        int r = row0 + ty * 4 + i;
#pragma unroll
        for (int jp = 0; jp < 3; jp++) {
            float v0, v1;
            unpack2(accp[i][jp], v0, v1);
            int c = tx * 6 + jp * 2;
#pragma unroll
            for (int h = 0; h < 2; h++) {
                float v = h ? v1 : v0;
                int cc = c + h;
                if (cc < DTRANK)
                    g_dpp[((size_t)ks * NROWS + r) * DTRANK + cc] = v;
                else
                    g_bcp[((size_t)ks * NROWS + r) * 32 + (cc - DTRANK)] = v;
            }
        }
    }
}

// ---------------------------------------------------------------------------
// K2 (fused GEMM2 + chunk-local scan), chunk-major state output.
// ---------------------------------------------------------------------------
__global__ __launch_bounds__(256)
void gemm2s_kernel(const float* __restrict__ x,
                   const float* __restrict__ dtw,
                   const float* __restrict__ dtb,
                   const float* __restrict__ te)
{
    __shared__ __align__(16) char smraw[44544];
    float (*dps)[34]    = (float(*)[34])  (smraw);               // 8704 B
    float (*ws)[132]    = (float(*)[132]) (smraw + 8704);        // 33792 B
    float (*sdelta)[132]= (float(*)[132]) (smraw + 8704);        // union w/ ws
    float (*sdu)[132]   = (float(*)[132]) (smraw + 8704 + 16896);
    float (*Bs)[16]     = (float(*)[16])  (smraw + 42496);       // 2048 B

    const int tid  = threadIdx.x;
    const int row0 = blockIdx.x * 32;
    const int by   = blockIdx.y;
    const int ty   = tid >> 4;
    const int tx   = tid & 15;

    // ---- Phase A: sum partials ----
#pragma unroll
    for (int i = 0; i < 2; i++) {
        int e  = i * 256 + tid;
        int r  = e >> 4;
        int k4 = e & 15;
        float4 s = make_float4(0.f, 0.f, 0.f, 0.f);
#pragma unroll
        for (int ks = 0; ks < KSPLIT; ks++) {
            float4 v = *(const float4*)&g_dpp[((size_t)ks * NROWS + row0 + r) * DTRANK + k4 * 4];
            s.x += v.x; s.y += v.y; s.z += v.z; s.w += v.w;
        }
        dps[k4 * 4 + 0][r] = s.x;
        dps[k4 * 4 + 1][r] = s.y;
        dps[k4 * 4 + 2][r] = s.z;
        dps[k4 * 4 + 3][r] = s.w;
    }
    {
        int r  = tid >> 3;
        int c4 = tid & 7;
        float4 s = make_float4(0.f, 0.f, 0.f, 0.f);
#pragma unroll
        for (int ks = 0; ks < KSPLIT; ks++) {
            float4 v = *(const float4*)&g_bcp[((size_t)ks * NROWS + row0 + r) * 32 + c4 * 4];
            s.x += v.x; s.y += v.y; s.z += v.z; s.w += v.w;
        }
        if (c4 < 4) {
            *(float4*)&Bs[r][c4 * 4] = s;
            if (by == 0) *(float4*)&g_bp[(size_t)(row0 + r) * DSTATE + c4 * 4] = s;
        } else if (by == 0) {
            *(float4*)&g_cp[(size_t)(row0 + r) * DSTATE + (c4 - 4) * 4] = s;
        }
    }
    // ---- load dtw tile ----
#pragma unroll
    for (int i = 0; i < 8; i++) {
        int e  = i * 256 + tid;
        int c  = e >> 4;
        int k4 = e & 15;
        float4 v = *(const float4*)&dtw[(size_t)(by * 128 + c) * DTRANK + k4 * 4];
        ws[k4 * 4 + 0][c] = v.x;
        ws[k4 * 4 + 1][c] = v.y;
        ws[k4 * 4 + 2][c] = v.z;
        ws[k4 * 4 + 3][c] = v.w;
    }
    __syncthreads();

    // ---- Phase B: f32x2 GEMM ----
    ull accp[2][4];
#pragma unroll
    for (int i = 0; i < 2; i++)
#pragma unroll
        for (int j = 0; j < 4; j++) accp[i][j] = 0ull;

#pragma unroll 16
    for (int k = 0; k < 64; k++) {
        float2 a01 = *(const float2*)&dps[k][ty * 2];
        ull a0p = pack2(a01.x, a01.x);
        ull a1p = pack2(a01.y, a01.y);
#pragma unroll
        for (int jp = 0; jp < 4; jp++) {
            ull wpv = *(const ull*)&ws[k][tx * 8 + jp * 2];
            accp[0][jp] = fma2(a0p, wpv, accp[0][jp]);
            accp[1][jp] = fma2(a1p, wpv, accp[1][jp]);
        }
    }
    __syncthreads();   // done reading ws; region becomes sdelta/sdu

    // ---- Phase C: epilogue ----
#pragma unroll
    for (int i = 0; i < 2; i++) {
        int lloc = ty * 2 + i;
        int r    = row0 + lloc;
        int c0   = by * 128 + tx * 8;
        float4 x0 = *(const float4*)&x[(size_t)r * DMODEL + c0];
        float4 x1 = *(const float4*)&x[(size_t)r * DMODEL + c0 + 4];
        float xv[8] = {x0.x, x0.y, x0.z, x0.w, x1.x, x1.y, x1.z, x1.w};
        float dl[8], du[8];
#pragma unroll
        for (int jp = 0; jp < 4; jp++) {
            float v0, v1;
            unpack2(accp[i][jp], v0, v1);
            float av[2] = {v0, v1};
#pragma unroll
            for (int h = 0; h < 2; h++) {
                int j = jp * 2 + h;
                int c = c0 + j;
                float sg = 1.f / (1.f + __expf(-te[c]));
                float u  = xv[j] * sg;
                float v  = av[h] + dtb[c];
                float delta = fmaxf(v, 0.f) + log1pf(__expf(-fabsf(v)));
                dl[j] = delta;
                du[j] = delta * u;
            }
        }
        float4* dst = (float4*)&g_dd[(size_t)r * DMODEL + c0];
#pragma unroll
        for (int j = 0; j < 4; j++)
            dst[j] = make_float4(dl[2*j], du[2*j], dl[2*j+1], du[2*j+1]);
        *(float4*)&sdelta[lloc][tx * 8]     = make_float4(dl[0], dl[1], dl[2], dl[3]);
        *(float4*)&sdelta[lloc][tx * 8 + 4] = make_float4(dl[4], dl[5], dl[6], dl[7]);
        *(float4*)&sdu[lloc][tx * 8]        = make_float4(du[0], du[1], du[2], du[3]);
        *(float4*)&sdu[lloc][tx * 8 + 4]    = make_float4(du[4], du[5], du[6], du[7]);
    }
    __syncthreads();

    // ---- Phase D: chunk-local scan (chunk-major output) ----
    {
        const int dloc = tid & 127;
        const int nh   = tid >> 7;              // state half
        const int b    = row0 >> 11;
        const int chunk= (row0 >> 5) & (NCHUNK - 1);
        const int d    = by * 128 + dloc;
        const size_t base = (size_t)chunk * NCH + b * DMODEL + d;

        float A[8];
#pragma unroll
        for (int j = 0; j < 8; j++) A[j] = g_A[(size_t)d * DSTATE + nh * 8 + j];
        bool uniform = true;
#pragma unroll
        for (int j = 1; j < 8; j++) uniform &= (A[j] == A[0]);

        ull hp[4] = {0ull, 0ull, 0ull, 0ull};
        float T = 0.f;

        if (uniform) {
            const float A0 = A[0];
#pragma unroll 4
            for (int l = 0; l < CLEN; l++) {
                float dx = sdelta[l][dloc];
                float dv = sdu[l][dloc];
                T += dx;
                float a = __expf(dx * A0);
                ull ap  = pack2(a, a);
                ull dup = pack2(dv, dv);
#pragma unroll
                for (int p = 0; p < 4; p++) {
                    ull bpr = *(const ull*)&Bs[l][nh * 8 + p * 2];
                    hp[p] = fma2(ap, hp[p], mul2(dup, bpr));
                }
            }
        } else {
#pragma unroll 2
            for (int l = 0; l < CLEN; l++) {
                float dx = sdelta[l][dloc];
                float dv = sdu[l][dloc];
                T += dx;
                ull dup = pack2(dv, dv);
#pragma unroll
                for (int p = 0; p < 4; p++) {
                    ull ap  = pack2(__expf(dx * A[p*2]), __expf(dx * A[p*2+1]));
                    ull bpr = *(const ull*)&Bs[l][nh * 8 + p * 2];
                    hp[p] = fma2(ap, hp[p], mul2(dup, bpr));
                }
            }
        }
#pragma unroll
        for (int p = 0; p < 4; p++)
            *(ull*)&g_hl[base * DSTATE + nh * 8 + p * 2] = hp[p];
        if (nh == 0) g_T[base] = T;
    }
}

// ---------------------------------------------------------------------------
// K3 (pass B): chunk combine, chunk-major (fully coalesced), MLP=8.
// ---------------------------------------------------------------------------
__global__ __launch_bounds__(256)
void scanB_kernel()
{
    const int idx = blockIdx.x * 256 + threadIdx.x;   // 32768
    const int ch  = idx >> 4;
    const int n   = idx & 15;
    const int d   = ch & (DMODEL - 1);

    const float A = g_A[(size_t)d * DSTATE + n];

    float hin = 0.f;
    for (int gblk = 0; gblk < NCHUNK / 8; gblk++) {
        float hl8[8], a8[8];
#pragma unroll
        for (int i = 0; i < 8; i++)
            hl8[i] = g_hl[((size_t)(gblk * 8 + i) * NCH + ch) * DSTATE + n];
#pragma unroll
        for (int i = 0; i < 8; i++)
            a8[i]  = __expf(g_T[(size_t)(gblk * 8 + i) * NCH + ch] * A);
#pragma unroll
        for (int i = 0; i < 8; i++) {
            g_hin[((size_t)(gblk * 8 + i) * NCH + ch) * DSTATE + n] = hin;
            hin = fmaf(hin, a8[i], hl8[i]);
        }
    }
}

// ---------------------------------------------------------------------------
// K4 (pass C): full re-scan with correct h0; u recovered as du/delta
//   (no x/te reads).  f32x2 packed states, MLP=8.
// ---------------------------------------------------------------------------
__global__ __launch_bounds__(256)
void scanC_kernel(const float* __restrict__ Dp,
                  float* __restrict__ out)
{
    __shared__ float Bs[CLEN][DSTATE];
    __shared__ float Cs[CLEN][DSTATE];

    const int tid   = threadIdx.x;
    const int blk   = blockIdx.x;
    const int b     = blk >> 8;
    const int rem   = blk & 255;
    const int dgrp  = rem >> 6;
    const int chunk = rem & 63;
    const int d     = dgrp * 256 + tid;
    const int ch    = b * DMODEL + d;
    const int l0    = chunk * CLEN;
    const size_t hbase = ((size_t)chunk * NCH + ch) * DSTATE;

    if (tid < CLEN * DSTATE / 4) {
        const float4* sb = (const float4*)&g_bp[((size_t)b * SEQLEN + l0) * DSTATE];
        ((float4*)Bs)[tid] = sb[tid];
    } else if (tid < CLEN * DSTATE / 2) {
        const float4* sc = (const float4*)&g_cp[((size_t)b * SEQLEN + l0) * DSTATE];
        ((float4*)Cs)[tid - CLEN * DSTATE / 4] = sc[tid - CLEN * DSTATE / 4];
    }

    float A[DSTATE];
#pragma unroll
    for (int n = 0; n < DSTATE; n++) A[n] = g_A[(size_t)d * DSTATE + n];
    bool uniform = true;
#pragma unroll
    for (int n = 1; n < DSTATE; n++) uniform &= (A[n] == A[0]);

    ull hp[8];
#pragma unroll
    for (int p = 0; p < 8; p++)
        hp[p] = *(const ull*)&g_hin[hbase + p * 2];

    const float Dpd = Dp[d];

    const float2* __restrict__ dd = g_dd + ((size_t)b * SEQLEN + l0) * DMODEL + d;
    float*        __restrict__ op = out  + ((size_t)b * SEQLEN + l0) * DMODEL + d;
    __syncthreads();

    if (uniform) {
        const float A0 = A[0];
        for (int lb = 0; lb < CLEN / 8; lb++) {
            float2 t[8];
#pragma unroll
            for (int i = 0; i < 8; i++) t[i] = dd[(size_t)(lb * 8 + i) * DMODEL];
            float a[8], u[8];
#pragma unroll
            for (int i = 0; i < 8; i++) {
                a[i] = __expf(t[i].x * A0);
                u[i] = __fdividef(t[i].y, fmaxf(t[i].x, 1e-38f));
            }
#pragma unroll
            for (int i = 0; i < 8; i++) {
                int l = lb * 8 + i;
                ull ap  = pack2(a[i], a[i]);
                ull dup = pack2(t[i].y, t[i].y);
                ull yp  = 0ull;
#pragma unroll
                for (int p = 0; p < 8; p++) {
                    ull bpr = *(const ull*)&Bs[l][p * 2];
                    ull cpr = *(const ull*)&Cs[l][p * 2];
                    hp[p] = fma2(ap, hp[p], mul2(dup, bpr));
                    yp    = fma2(hp[p], cpr, yp);
                }
                float ylo, yhi;
                unpack2(yp, ylo, yhi);
                op[(size_t)l * DMODEL] = fmaf(u[i], Dpd, ylo + yhi);
            }
        }
    } else {
        for (int lb = 0; lb < CLEN / 8; lb++) {
            float2 t[8];
#pragma unroll
            for (int i = 0; i < 8; i++) t[i] = dd[(size_t)(lb * 8 + i) * DMODEL];
            float u[8];
#pragma unroll
            for (int i = 0; i < 8; i++)
                u[i] = __fdividef(t[i].y, fmaxf(t[i].x, 1e-38f));
#pragma unroll
            for (int i = 0; i < 8; i++) {
                int l = lb * 8 + i;
                ull dup = pack2(t[i].y, t[i].y);
                ull yp  = 0ull;
#pragma unroll
                for (int p = 0; p < 8; p++) {
                    ull ap  = pack2(__expf(t[i].x * A[p*2]), __expf(t[i].x * A[p*2+1]));
                    ull bpr = *(const ull*)&Bs[l][p * 2];
                    ull cpr = *(const ull*)&Cs[l][p * 2];
                    hp[p] = fma2(ap, hp[p], mul2(dup, bpr));
                    yp    = fma2(hp[p], cpr, yp);
                }
                float ylo, yhi;
                unpack2(yp, ylo, yhi);
                op[(size_t)l * DMODEL] = fmaf(u[i], Dpd, ylo + yhi);
            }
        }
    }
}

// ---------------------------------------------------------------------------
// Launch
// ---------------------------------------------------------------------------
extern "C" void kernel_launch(void* const* d_in, const int* in_sizes, int n_in,
                              void* d_out, int out_size)
{
    const float* x    = (const float*)d_in[0];
    const float* Alog = (const float*)d_in[1];
    const float* xpw  = (const float*)d_in[2];
    const float* dtw  = (const float*)d_in[3];
    const float* dtb  = (const float*)d_in[4];
    const float* Dp   = (const float*)d_in[5];
    const float* te   = (const float*)d_in[6];
    float* out = (float*)d_out;

    prep_kernel  <<<(96 * DMODEL + 255) / 256, 256>>>(xpw, te, Alog);
    gemm1_kernel <<<dim3(NROWS / 64, KSPLIT), 256>>>(x);
    gemm2s_kernel<<<dim3(NROWS / 32, DMODEL / 128), 256>>>(x, dtw, dtb, te);
    scanB_kernel <<<(NCH * DSTATE) / 256, 256>>>();
    scanC_kernel <<<BATCH * 4 * NCHUNK, 256>>>(Dp, out);
}